// round 2
// baseline (speedup 1.0000x reference)
#include <cuda_runtime.h>
#include <math.h>

#define B 32
#define S 512
#define D 1536
#define D24 64
#define KF 10

// Scratch (device globals — no allocation allowed in kernel_launch)
__device__ float g_xn[(size_t)B * S * D];   // layernorm output
__device__ float g_acc[B * KF];             // gating partial sums (atomic)
__device__ int   g_sel[B];                  // per-batch gate decision

__device__ __forceinline__ float gelu_f(float v) {
    // exact gelu: x * Phi(x)
    return 0.5f * v * (1.0f + erff(v * 0.7071067811865476f));
}

__global__ void k_zero() {
    int t = threadIdx.x;
    if (t < B * KF) g_acc[t] = 0.0f;
}

// One block per (b,s) row: LayerNorm + gating feature h = gelu(c@w1+b1),
// accumulate wc[s]*h into per-batch accumulator.
__global__ __launch_bounds__(256)
void k_ln(const float* __restrict__ x,
          const float* __restrict__ ln_g, const float* __restrict__ ln_b,
          const float* __restrict__ w1,   const float* __restrict__ b1,
          const float* __restrict__ wc)
{
    __shared__ float sh[D];
    __shared__ float rsum[8], rsq[8];
    __shared__ float s_mu, s_rs;

    int row = blockIdx.x;          // 0..B*S-1
    int b   = row >> 9;
    int s   = row & 511;
    const float* xr = x + (size_t)row * D;
    int t = threadIdx.x;

    float v[6];
    float sum = 0.f, sq = 0.f;
#pragma unroll
    for (int i = 0; i < 6; i++) {
        v[i] = xr[t + 256 * i];
        sum += v[i];
        sq  += v[i] * v[i];
    }
#pragma unroll
    for (int o = 16; o; o >>= 1) {
        sum += __shfl_xor_sync(0xffffffffu, sum, o);
        sq  += __shfl_xor_sync(0xffffffffu, sq,  o);
    }
    if ((t & 31) == 0) { rsum[t >> 5] = sum; rsq[t >> 5] = sq; }
    __syncthreads();
    if (t == 0) {
        float ts = 0.f, tq = 0.f;
#pragma unroll
        for (int i = 0; i < 8; i++) { ts += rsum[i]; tq += rsq[i]; }
        float mu  = ts * (1.0f / D);
        float var = tq * (1.0f / D) - mu * mu;
        s_mu = mu;
        s_rs = rsqrtf(var + 1e-5f);
    }
    __syncthreads();
    float mu = s_mu, rs = s_rs;

    float* xnr = g_xn + (size_t)row * D;
#pragma unroll
    for (int i = 0; i < 6; i++) {
        int idx = t + 256 * i;
        float xn = (v[i] - mu) * rs * ln_g[idx] + ln_b[idx];
        sh[idx] = xn;
        xnr[idx] = xn;
    }
    __syncthreads();

    if (t < KF) {
        float d = b1[t];
#pragma unroll
        for (int j = 0; j < D24; j++) d += sh[j] * w1[j * KF + t];
        float h = gelu_f(d);
        atomicAdd(&g_acc[b * KF + t], wc[s] * h);
    }
}

// Per-batch gate decision
__global__ void k_gate(const float* __restrict__ bc,
                       const float* __restrict__ w2,
                       const float* __restrict__ b2)
{
    int b = threadIdx.x;
    if (b < B) {
        float bcv = bc[0];
        float lg = b2[0];
#pragma unroll
        for (int k = 0; k < KF; k++)
            lg += gelu_f(g_acc[b * KF + k] + bcv) * w2[k];
        float g = 1.0f / (1.0f + expf(-lg));
        g_sel[b] = (rintf(g) != 0.0f) ? 1 : 0;
    }
}

// Per batch: out = gelu(Wsel @ xn + bsel + x)
// C[s,d] = sum_t W[s,t] * X[t,d]; M=512, N=1536, K=512.
// 128x128 block tile, BK=16, 256 threads, 8x8 per thread (split 4+4 strided).
__global__ __launch_bounds__(256, 2)
void k_gemm(const float* __restrict__ Wi, const float* __restrict__ Wii,
            const float* __restrict__ bi, const float* __restrict__ bii,
            const float* __restrict__ x,  float* __restrict__ out)
{
    __shared__ float As[16][128];   // transposed: As[k][m]
    __shared__ float Bs[16][128];   // Bs[k][n]

    int bb = blockIdx.z;
    int sel = g_sel[bb];
    const float* W  = sel ? Wii : Wi;
    const float* bv = sel ? bii : bi;
    const float* X  = g_xn + (size_t)bb * S * D;
    const float* xr = x    + (size_t)bb * S * D;
    float* o        = out  + (size_t)bb * S * D;

    int m0 = blockIdx.y * 128;
    int n0 = blockIdx.x * 128;
    int t  = threadIdx.x;
    int tx = t & 15, ty = t >> 4;

    float acc[8][8];
#pragma unroll
    for (int i = 0; i < 8; i++)
#pragma unroll
        for (int j = 0; j < 8; j++) acc[i][j] = 0.0f;

    for (int k0 = 0; k0 < 512; k0 += 16) {
#pragma unroll
        for (int l = 0; l < 2; l++) {
            int idx = t + l * 256;
            // A tile: 128 rows x 16 k, one float4 along k, store transposed
            int ar = idx >> 2, ak = (idx & 3) << 2;
            float4 av = *(const float4*)(W + (size_t)(m0 + ar) * 512 + k0 + ak);
            As[ak + 0][ar] = av.x; As[ak + 1][ar] = av.y;
            As[ak + 2][ar] = av.z; As[ak + 3][ar] = av.w;
            // B tile: 16 rows x 128 n, direct float4
            int br = idx >> 5, bc = (idx & 31) << 2;
            *(float4*)&Bs[br][bc] =
                *(const float4*)(X + (size_t)(k0 + br) * D + n0 + bc);
        }
        __syncthreads();
#pragma unroll
        for (int kk = 0; kk < 16; kk++) {
            float a[8], bf[8];
#pragma unroll
            for (int i = 0; i < 4; i++) {
                a[i]      = As[kk][ty * 4 + i];
                a[4 + i]  = As[kk][64 + ty * 4 + i];
                bf[i]     = Bs[kk][tx * 4 + i];
                bf[4 + i] = Bs[kk][64 + tx * 4 + i];
            }
#pragma unroll
            for (int i = 0; i < 8; i++)
#pragma unroll
                for (int j = 0; j < 8; j++)
                    acc[i][j] += a[i] * bf[j];
        }
        __syncthreads();
    }

    // Epilogue: + bias + residual, gelu, store
#pragma unroll
    for (int i = 0; i < 8; i++) {
        int r = m0 + ((i < 4) ? (ty * 4 + i) : (64 + ty * 4 + (i - 4)));
        float bias = bv[r];
#pragma unroll
        for (int jh = 0; jh < 2; jh++) {
            int c = n0 + ((jh == 0) ? (tx * 4) : (64 + tx * 4));
            size_t off = (size_t)r * D + c;
            float4 xv = *(const float4*)(xr + off);
            float4 ov;
            ov.x = gelu_f(acc[i][jh * 4 + 0] + bias + xv.x);
            ov.y = gelu_f(acc[i][jh * 4 + 1] + bias + xv.y);
            ov.z = gelu_f(acc[i][jh * 4 + 2] + bias + xv.z);
            ov.w = gelu_f(acc[i][jh * 4 + 3] + bias + xv.w);
            *(float4*)(o + off) = ov;
        }
    }
}

extern "C" void kernel_launch(void* const* d_in, const int* in_sizes, int n_in,
                              void* d_out, int out_size)
{
    const float* x    = (const float*)d_in[0];
    const float* ln_g = (const float*)d_in[1];
    const float* ln_b = (const float*)d_in[2];
    const float* w1   = (const float*)d_in[3];
    const float* b1   = (const float*)d_in[4];
    const float* wc   = (const float*)d_in[5];
    const float* bc   = (const float*)d_in[6];
    const float* w2   = (const float*)d_in[7];
    const float* b2   = (const float*)d_in[8];
    const float* Wi   = (const float*)d_in[9];
    const float* bi   = (const float*)d_in[10];
    const float* Wii  = (const float*)d_in[11];
    const float* bii  = (const float*)d_in[12];
    float* out = (float*)d_out;

    k_zero<<<1, 320>>>();
    k_ln<<<B * S, 256>>>(x, ln_g, ln_b, w1, b1, wc);
    k_gate<<<1, 32>>>(bc, w2, b2);
    k_gemm<<<dim3(12, 4, B), 256>>>(Wi, Wii, bi, bii, x, out);
}

// round 7
// speedup vs baseline: 2.0706x; 2.0706x over previous
#include <cuda_runtime.h>
#include <cuda_bf16.h>
#include <math.h>
#include <stdint.h>

#define B 32
#define S 512
#define D 1536
#define D24 64
#define KF 10

// ---------------- device scratch (no allocation allowed) ----------------
__device__ __nv_bfloat16 g_xhi[(size_t)B * S * D];
__device__ __nv_bfloat16 g_xlo[(size_t)B * S * D];
__device__ __nv_bfloat16 g_whi[2 * S * S];
__device__ __nv_bfloat16 g_wlo[2 * S * S];
__device__ float g_acc[B * KF];
__device__ int   g_sel[B];

__device__ __forceinline__ float gelu_f(float v) {
    return 0.5f * v * (1.0f + erff(v * 0.7071067811865476f));
}
__device__ __forceinline__ uint32_t smem_u32(const void* p) {
    uint32_t a;
    asm("{ .reg .u64 t; cvta.to.shared.u64 t, %1; cvt.u32.u64 %0, t; }" : "=r"(a) : "l"(p));
    return a;
}

// ---------------- small kernels ----------------
__global__ void k_zero() {
    int t = threadIdx.x;
    if (t < B * KF) g_acc[t] = 0.0f;
}

__global__ void k_split(const float* __restrict__ Wi, const float* __restrict__ Wii) {
    int i = blockIdx.x * 256 + threadIdx.x;   // 0..262143
    float a = Wi[i];
    __nv_bfloat16 h = __float2bfloat16(a);
    g_whi[i] = h;
    g_wlo[i] = __float2bfloat16(a - __bfloat162float(h));
    float b = Wii[i];
    __nv_bfloat16 h2 = __float2bfloat16(b);
    g_whi[S * S + i] = h2;
    g_wlo[S * S + i] = __float2bfloat16(b - __bfloat162float(h2));
}

__global__ __launch_bounds__(256)
void k_ln(const float* __restrict__ x,
          const float* __restrict__ ln_g, const float* __restrict__ ln_b,
          const float* __restrict__ w1,   const float* __restrict__ b1,
          const float* __restrict__ wc)
{
    __shared__ float sh[D];
    __shared__ float rsum[8], rsq[8];
    __shared__ float s_mu, s_rs;

    int row = blockIdx.x;
    int b   = row >> 9;
    int s   = row & 511;
    const float* xr = x + (size_t)row * D;
    int t = threadIdx.x;

    float v[6];
    float sum = 0.f, sq = 0.f;
#pragma unroll
    for (int i = 0; i < 6; i++) {
        v[i] = xr[t + 256 * i];
        sum += v[i];
        sq  += v[i] * v[i];
    }
#pragma unroll
    for (int o = 16; o; o >>= 1) {
        sum += __shfl_xor_sync(0xffffffffu, sum, o);
        sq  += __shfl_xor_sync(0xffffffffu, sq,  o);
    }
    if ((t & 31) == 0) { rsum[t >> 5] = sum; rsq[t >> 5] = sq; }
    __syncthreads();
    if (t == 0) {
        float ts = 0.f, tq = 0.f;
#pragma unroll
        for (int i = 0; i < 8; i++) { ts += rsum[i]; tq += rsq[i]; }
        float mu  = ts * (1.0f / D);
        float var = tq * (1.0f / D) - mu * mu;
        s_mu = mu;
        s_rs = rsqrtf(var + 1e-5f);
    }
    __syncthreads();
    float mu = s_mu, rs = s_rs;

    __nv_bfloat16* xh = g_xhi + (size_t)row * D;
    __nv_bfloat16* xl = g_xlo + (size_t)row * D;
#pragma unroll
    for (int i = 0; i < 6; i++) {
        int idx = t + 256 * i;
        float xn = (v[i] - mu) * rs * ln_g[idx] + ln_b[idx];
        sh[idx] = xn;
        __nv_bfloat16 h = __float2bfloat16(xn);
        xh[idx] = h;
        xl[idx] = __float2bfloat16(xn - __bfloat162float(h));
    }
    __syncthreads();

    if (t < KF) {
        float d = b1[t];
#pragma unroll
        for (int j = 0; j < D24; j++) d += sh[j] * w1[j * KF + t];
        float h = gelu_f(d);
        atomicAdd(&g_acc[b * KF + t], wc[s] * h);
    }
}

__global__ void k_gate(const float* __restrict__ bc,
                       const float* __restrict__ w2,
                       const float* __restrict__ b2)
{
    int b = threadIdx.x;
    if (b < B) {
        float bcv = bc[0];
        float lg = b2[0];
#pragma unroll
        for (int k = 0; k < KF; k++)
            lg += gelu_f(g_acc[b * KF + k] + bcv) * w2[k];
        float g = 1.0f / (1.0f + expf(-lg));
        g_sel[b] = (rintf(g) != 0.0f) ? 1 : 0;
    }
}

// ---------------- HMMA (mma.sync bf16) GEMM ----------------
// Per batch: C[s,d] = sum_t Wsel[s,t] * xn[t,d]; out = gelu(C + bias + residual)
// CTA 128x128, BK=32, 256 thr / 8 warps, warp tile 64x32, split-bf16 (3 MMAs).
#define BM 128
#define BN 128
#define BK 32
#define A_STRIDE 40                      // bf16 per A row (32 + 8 pad) = 80B
#define B_STRIDE 136                     // bf16 per B row (128 + 8 pad) = 272B
#define A_SPL_BYTES (128 * A_STRIDE * 2) // 10240
#define B_SPL_BYTES (32 * B_STRIDE * 2)  // 8704
#define STAGE_BYTES (2 * A_SPL_BYTES + 2 * B_SPL_BYTES) // 37888
#define SMEM_BYTES (2 * STAGE_BYTES)     // 75776 (epilogue reuses as 128x132 f32)

#define LDSM_X4(r0, r1, r2, r3, a) \
    asm volatile("ldmatrix.sync.aligned.m8n8.x4.shared.b16 {%0,%1,%2,%3}, [%4];" \
        : "=r"(r0), "=r"(r1), "=r"(r2), "=r"(r3) : "r"(a))
#define LDSM_X4_T(r0, r1, r2, r3, a) \
    asm volatile("ldmatrix.sync.aligned.m8n8.x4.trans.shared.b16 {%0,%1,%2,%3}, [%4];" \
        : "=r"(r0), "=r"(r1), "=r"(r2), "=r"(r3) : "r"(a))
#define MMA16816(c, a, b0, b1) \
    asm volatile("mma.sync.aligned.m16n8k16.row.col.f32.bf16.bf16.f32 " \
        "{%0,%1,%2,%3}, {%4,%5,%6,%7}, {%8,%9}, {%0,%1,%2,%3};" \
        : "+f"((c)[0]), "+f"((c)[1]), "+f"((c)[2]), "+f"((c)[3]) \
        : "r"((a)[0]), "r"((a)[1]), "r"((a)[2]), "r"((a)[3]), "r"(b0), "r"(b1))
#define CP_ASYNC16(dst, src) \
    asm volatile("cp.async.cg.shared.global [%0], [%1], 16;" :: "r"(dst), "l"(src))

__global__ __launch_bounds__(256)
void k_gemm_mma(const float* __restrict__ bi, const float* __restrict__ bii,
                const float* __restrict__ x,  float* __restrict__ out)
{
    extern __shared__ char smem[];
    uint32_t sb = smem_u32(smem);
    int t = threadIdx.x;
    int lane = t & 31;
    int wid = t >> 5;
    int wm = wid >> 2;        // 0..1 -> m offset wm*64
    int wn = wid & 3;         // 0..3 -> n offset wn*32
    int bb = blockIdx.z;
    int m0 = blockIdx.y * BM;
    int n0 = blockIdx.x * BN;

    int sel = g_sel[bb];
    const __nv_bfloat16* wh = g_whi + (size_t)sel * S * S;
    const __nv_bfloat16* wl = g_wlo + (size_t)sel * S * S;
    const float* bv = sel ? bii : bi;
    const __nv_bfloat16* xh = g_xhi + (size_t)bb * S * D;
    const __nv_bfloat16* xl = g_xlo + (size_t)bb * S * D;

    // ---- async stage loader ----
    auto load_stage = [&](int c, int st) {
        int k0 = c * BK;
        uint32_t base = sb + st * STAGE_BYTES;
#pragma unroll
        for (int i = 0; i < 4; i++) {           // A: 1024 x 16B
            int idx = t + 256 * i;
            int spl = idx >> 9; int rem = idx & 511;
            int row = rem >> 2, seg = rem & 3;
            const __nv_bfloat16* src = (spl ? wl : wh) + (size_t)(m0 + row) * S + k0 + seg * 8;
            uint32_t dst = base + spl * A_SPL_BYTES + (row * A_STRIDE + seg * 8) * 2;
            CP_ASYNC16(dst, src);
        }
#pragma unroll
        for (int i = 0; i < 4; i++) {           // B: 1024 x 16B
            int idx = t + 256 * i;
            int spl = idx >> 9; int rem = idx & 511;
            int row = rem >> 4, seg = rem & 15;
            const __nv_bfloat16* src = (spl ? xl : xh) + (size_t)(k0 + row) * D + n0 + seg * 8;
            uint32_t dst = base + 2 * A_SPL_BYTES + spl * B_SPL_BYTES + (row * B_STRIDE + seg * 8) * 2;
            CP_ASYNC16(dst, src);
        }
        asm volatile("cp.async.commit_group;");
    };

    float acc[4][4][4];
#pragma unroll
    for (int i = 0; i < 4; i++)
#pragma unroll
        for (int j = 0; j < 4; j++)
#pragma unroll
            for (int k = 0; k < 4; k++) acc[i][j][k] = 0.f;

    load_stage(0, 0);

    for (int c = 0; c < 16; c++) {
        int st = c & 1;
        if (c + 1 < 16) {
            load_stage(c + 1, st ^ 1);
            asm volatile("cp.async.wait_group 1;");
        } else {
            asm volatile("cp.async.wait_group 0;");
        }
        __syncthreads();

        uint32_t base = sb + st * STAGE_BYTES;
#pragma unroll
        for (int ks = 0; ks < 2; ks++) {
            int kc = ks * 16 + (lane >> 4) * 8;           // ldmatrix k col
            uint32_t ah[4][4], al[4][4];
#pragma unroll
            for (int mt = 0; mt < 4; mt++) {
                int row = wm * 64 + mt * 16 + (lane & 15);
                uint32_t ad = base + (row * A_STRIDE + kc) * 2;
                LDSM_X4(ah[mt][0], ah[mt][1], ah[mt][2], ah[mt][3], ad);
                LDSM_X4(al[mt][0], al[mt][1], al[mt][2], al[mt][3], ad + A_SPL_BYTES);
            }
            uint32_t bh[2][4], bl[2][4];
#pragma unroll
            for (int np = 0; np < 2; np++) {
                int krow = ks * 16 + (lane & 15);
                int coln = wn * 32 + np * 16 + (lane >> 4) * 8;
                uint32_t bd = base + 2 * A_SPL_BYTES + (krow * B_STRIDE + coln) * 2;
                LDSM_X4_T(bh[np][0], bh[np][1], bh[np][2], bh[np][3], bd);
                LDSM_X4_T(bl[np][0], bl[np][1], bl[np][2], bl[np][3], bd + B_SPL_BYTES);
            }
#pragma unroll
            for (int mt = 0; mt < 4; mt++)
#pragma unroll
                for (int nt = 0; nt < 4; nt++) {
                    int np = nt >> 1, wq = (nt & 1) * 2;
                    MMA16816(acc[mt][nt], ah[mt], bh[np][wq], bh[np][wq + 1]); // hi*hi
                    MMA16816(acc[mt][nt], ah[mt], bl[np][wq], bl[np][wq + 1]); // hi*lo
                    MMA16816(acc[mt][nt], al[mt], bh[np][wq], bh[np][wq + 1]); // lo*hi
                }
        }
        __syncthreads();
    }

    // ---- epilogue: stage C in SMEM (stride 132 f32), then coalesced out ----
    float* cs = (float*)smem;
#pragma unroll
    for (int mt = 0; mt < 4; mt++)
#pragma unroll
        for (int nt = 0; nt < 4; nt++) {
            int r = wm * 64 + mt * 16 + (lane >> 2);
            int cc = wn * 32 + nt * 8 + (lane & 3) * 2;
            cs[r * 132 + cc]           = acc[mt][nt][0];
            cs[r * 132 + cc + 1]       = acc[mt][nt][1];
            cs[(r + 8) * 132 + cc]     = acc[mt][nt][2];
            cs[(r + 8) * 132 + cc + 1] = acc[mt][nt][3];
        }
    __syncthreads();

#pragma unroll
    for (int i = 0; i < 16; i++) {
        int idx = t + 256 * i;           // 4096 float4s
        int r = idx >> 5, c4 = (idx & 31) * 4;
        float bias = bv[m0 + r];
        size_t off = ((size_t)bb * S + m0 + r) * D + n0 + c4;
        float4 xv = *(const float4*)(x + off);
        float4 ov;
        ov.x = gelu_f(cs[r * 132 + c4 + 0] + bias + xv.x);
        ov.y = gelu_f(cs[r * 132 + c4 + 1] + bias + xv.y);
        ov.z = gelu_f(cs[r * 132 + c4 + 2] + bias + xv.z);
        ov.w = gelu_f(cs[r * 132 + c4 + 3] + bias + xv.w);
        *(float4*)(out + off) = ov;
    }
}

// ---------------- launch ----------------
extern "C" void kernel_launch(void* const* d_in, const int* in_sizes, int n_in,
                              void* d_out, int out_size)
{
    const float* x    = (const float*)d_in[0];
    const float* ln_g = (const float*)d_in[1];
    const float* ln_b = (const float*)d_in[2];
    const float* w1   = (const float*)d_in[3];
    const float* b1   = (const float*)d_in[4];
    const float* wc   = (const float*)d_in[5];
    const float* bc   = (const float*)d_in[6];
    const float* w2   = (const float*)d_in[7];
    const float* b2   = (const float*)d_in[8];
    const float* Wi   = (const float*)d_in[9];
    const float* bi   = (const float*)d_in[10];
    const float* Wii  = (const float*)d_in[11];
    const float* bii  = (const float*)d_in[12];
    float* out = (float*)d_out;

    cudaFuncSetAttribute(k_gemm_mma, cudaFuncAttributeMaxDynamicSharedMemorySize, SMEM_BYTES);

    k_zero<<<1, 320>>>();
    k_split<<<S * S / 256, 256>>>(Wi, Wii);
    k_ln<<<B * S, 256>>>(x, ln_g, ln_b, w1, b1, wc);
    k_gate<<<1, 32>>>(bc, w2, b2);
    k_gemm_mma<<<dim3(D / BN, S / BM, B), 256, SMEM_BYTES>>>(bi, bii, x, out);
}

// round 9
// speedup vs baseline: 2.6462x; 1.2780x over previous
#include <cuda_runtime.h>
#include <cuda_bf16.h>
#include <cuda_fp16.h>
#include <math.h>
#include <stdint.h>

#define B 32
#define S 512
#define D 1536
#define D24 64
#define KF 10

// ---------------- device scratch (no allocation allowed) ----------------
__device__ __half g_xh[(size_t)B * S * D];   // xn in fp16
__device__ __half g_wh[2 * S * S];           // W hi (fp16)
__device__ __half g_wl[2 * S * S];           // W lo (fp16 residual)
__device__ float g_acc[B * KF];
__device__ int   g_sel[B];

__device__ __forceinline__ float gelu_f(float v) {
    return 0.5f * v * (1.0f + erff(v * 0.7071067811865476f));
}
__device__ __forceinline__ uint32_t smem_u32(const void* p) {
    uint32_t a;
    asm("{ .reg .u64 t; cvta.to.shared.u64 t, %1; cvt.u32.u64 %0, t; }" : "=r"(a) : "l"(p));
    return a;
}

// ---------------- small kernels ----------------
__global__ void k_zero() {
    int t = threadIdx.x;
    if (t < B * KF) g_acc[t] = 0.0f;
}

__global__ void k_split(const float* __restrict__ Wi, const float* __restrict__ Wii) {
    int i = blockIdx.x * 256 + threadIdx.x;   // 0..262143
    float a = Wi[i];
    __half h = __float2half_rn(a);
    g_wh[i] = h;
    g_wl[i] = __float2half_rn(a - __half2float(h));
    float b = Wii[i];
    __half h2 = __float2half_rn(b);
    g_wh[S * S + i] = h2;
    g_wl[S * S + i] = __float2half_rn(b - __half2float(h2));
}

__global__ __launch_bounds__(256)
void k_ln(const float* __restrict__ x,
          const float* __restrict__ ln_g, const float* __restrict__ ln_b,
          const float* __restrict__ w1,   const float* __restrict__ b1,
          const float* __restrict__ wc)
{
    __shared__ float sh[D];
    __shared__ float rsum[8], rsq[8];
    __shared__ float s_mu, s_rs;

    int row = blockIdx.x;
    int b   = row >> 9;
    int s   = row & 511;
    const float* xr = x + (size_t)row * D;
    int t = threadIdx.x;

    float v[6];
    float sum = 0.f, sq = 0.f;
#pragma unroll
    for (int i = 0; i < 6; i++) {
        v[i] = xr[t + 256 * i];
        sum += v[i];
        sq  += v[i] * v[i];
    }
#pragma unroll
    for (int o = 16; o; o >>= 1) {
        sum += __shfl_xor_sync(0xffffffffu, sum, o);
        sq  += __shfl_xor_sync(0xffffffffu, sq,  o);
    }
    if ((t & 31) == 0) { rsum[t >> 5] = sum; rsq[t >> 5] = sq; }
    __syncthreads();
    if (t == 0) {
        float ts = 0.f, tq = 0.f;
#pragma unroll
        for (int i = 0; i < 8; i++) { ts += rsum[i]; tq += rsq[i]; }
        float mu  = ts * (1.0f / D);
        float var = tq * (1.0f / D) - mu * mu;
        s_mu = mu;
        s_rs = rsqrtf(var + 1e-5f);
    }
    __syncthreads();
    float mu = s_mu, rs = s_rs;

    __half* xh = g_xh + (size_t)row * D;
#pragma unroll
    for (int i = 0; i < 6; i++) {
        int idx = t + 256 * i;
        float xn = (v[i] - mu) * rs * ln_g[idx] + ln_b[idx];
        sh[idx] = xn;
        xh[idx] = __float2half_rn(xn);
    }
    __syncthreads();

    if (t < KF) {
        float d = b1[t];
#pragma unroll
        for (int j = 0; j < D24; j++) d += sh[j] * w1[j * KF + t];
        float h = gelu_f(d);
        atomicAdd(&g_acc[b * KF + t], wc[s] * h);
    }
}

__global__ void k_gate(const float* __restrict__ bc,
                       const float* __restrict__ w2,
                       const float* __restrict__ b2)
{
    int b = threadIdx.x;
    if (b < B) {
        float bcv = bc[0];
        float lg = b2[0];
#pragma unroll
        for (int k = 0; k < KF; k++)
            lg += gelu_f(g_acc[b * KF + k] + bcv) * w2[k];
        float g = 1.0f / (1.0f + expf(-lg));
        g_sel[b] = (rintf(g) != 0.0f) ? 1 : 0;
    }
}

// ---------------- HMMA (mma.sync fp16) GEMM ----------------
// Per batch: C[s,d] = sum_t Wsel[s,t] * xn[t,d]; out = gelu(C + bias + residual)
// CTA 128x128, BK=32, 256 thr / 8 warps, warp tile 64x32.
// 2-term fp16 split: C = Whi*X + Wlo*X (X single fp16).
#define BM 128
#define BN 128
#define BK 32
#define A_STRIDE 40                      // fp16 per A row (32 + 8 pad) = 80B
#define B_STRIDE 136                     // fp16 per B row (128 + 8 pad) = 272B
#define A_SPL_BYTES (128 * A_STRIDE * 2) // 10240
#define B_TILE_BYTES (32 * B_STRIDE * 2) // 8704
#define STAGE_BYTES (2 * A_SPL_BYTES + B_TILE_BYTES) // 29184
#define SMEM_BYTES (3 * STAGE_BYTES)     // 87552 (epilogue reuse: 128*132*4 = 67584)

#define LDSM_X4(r0, r1, r2, r3, a) \
    asm volatile("ldmatrix.sync.aligned.m8n8.x4.shared.b16 {%0,%1,%2,%3}, [%4];" \
        : "=r"(r0), "=r"(r1), "=r"(r2), "=r"(r3) : "r"(a))
#define LDSM_X4_T(r0, r1, r2, r3, a) \
    asm volatile("ldmatrix.sync.aligned.m8n8.x4.trans.shared.b16 {%0,%1,%2,%3}, [%4];" \
        : "=r"(r0), "=r"(r1), "=r"(r2), "=r"(r3) : "r"(a))
#define MMA16816(c, a, b0, b1) \
    asm volatile("mma.sync.aligned.m16n8k16.row.col.f32.f16.f16.f32 " \
        "{%0,%1,%2,%3}, {%4,%5,%6,%7}, {%8,%9}, {%0,%1,%2,%3};" \
        : "+f"((c)[0]), "+f"((c)[1]), "+f"((c)[2]), "+f"((c)[3]) \
        : "r"((a)[0]), "r"((a)[1]), "r"((a)[2]), "r"((a)[3]), "r"(b0), "r"(b1))
#define CP_ASYNC16(dst, src) \
    asm volatile("cp.async.cg.shared.global [%0], [%1], 16;" :: "r"(dst), "l"(src))

__global__ __launch_bounds__(256)
void k_gemm_mma(const float* __restrict__ bi, const float* __restrict__ bii,
                const float* __restrict__ x,  float* __restrict__ out)
{
    extern __shared__ char smem[];
    uint32_t sb = smem_u32(smem);
    int t = threadIdx.x;
    int lane = t & 31;
    int wid = t >> 5;
    int wm = wid >> 2;        // 0..1 -> m offset wm*64
    int wn = wid & 3;         // 0..3 -> n offset wn*32
    int bb = blockIdx.z;
    int m0 = blockIdx.y * BM;
    int n0 = blockIdx.x * BN;

    int sel = g_sel[bb];
    const __half* wh = g_wh + (size_t)sel * S * S;
    const __half* wl = g_wl + (size_t)sel * S * S;
    const float* bv = sel ? bii : bi;
    const __half* xh = g_xh + (size_t)bb * S * D;

    // ---- async stage loader (6 x 16B per thread) ----
    auto load_stage = [&](int c, int st) {
        int k0 = c * BK;
        uint32_t base = sb + st * STAGE_BYTES;
#pragma unroll
        for (int i = 0; i < 4; i++) {           // A hi+lo: 1024 x 16B
            int idx = t + 256 * i;
            int spl = idx >> 9; int rem = idx & 511;
            int row = rem >> 2, seg = rem & 3;
            const __half* src = (spl ? wl : wh) + (size_t)(m0 + row) * S + k0 + seg * 8;
            uint32_t dst = base + spl * A_SPL_BYTES + (row * A_STRIDE + seg * 8) * 2;
            CP_ASYNC16(dst, src);
        }
#pragma unroll
        for (int i = 0; i < 2; i++) {           // B: 512 x 16B
            int idx = t + 256 * i;
            int row = idx >> 4, seg = idx & 15;
            const __half* src = xh + (size_t)(k0 + row) * D + n0 + seg * 8;
            uint32_t dst = base + 2 * A_SPL_BYTES + (row * B_STRIDE + seg * 8) * 2;
            CP_ASYNC16(dst, src);
        }
        asm volatile("cp.async.commit_group;");
    };

    float acc[4][4][4];
#pragma unroll
    for (int i = 0; i < 4; i++)
#pragma unroll
        for (int j = 0; j < 4; j++)
#pragma unroll
            for (int k = 0; k < 4; k++) acc[i][j][k] = 0.f;

    load_stage(0, 0);
    load_stage(1, 1);

    for (int c = 0; c < 16; c++) {
        int st = c % 3;
        // group c must be complete; group c+1 may stay in flight
        asm volatile("cp.async.wait_group 1;");
        __syncthreads();   // data of stage c visible; all warps done with stage (c-1)%3
        if (c + 2 < 16) load_stage(c + 2, (c + 2) % 3);

        uint32_t base = sb + st * STAGE_BYTES;
#pragma unroll
        for (int ks = 0; ks < 2; ks++) {
            int kc = ks * 16 + (lane >> 4) * 8;           // ldmatrix k col
            uint32_t ah[4][4], al[4][4];
#pragma unroll
            for (int mt = 0; mt < 4; mt++) {
                int row = wm * 64 + mt * 16 + (lane & 15);
                uint32_t ad = base + (row * A_STRIDE + kc) * 2;
                LDSM_X4(ah[mt][0], ah[mt][1], ah[mt][2], ah[mt][3], ad);
                LDSM_X4(al[mt][0], al[mt][1], al[mt][2], al[mt][3], ad + A_SPL_BYTES);
            }
            uint32_t bh[2][4];
#pragma unroll
            for (int np = 0; np < 2; np++) {
                int krow = ks * 16 + (lane & 15);
                int coln = wn * 32 + np * 16 + (lane >> 4) * 8;
                uint32_t bd = base + 2 * A_SPL_BYTES + (krow * B_STRIDE + coln) * 2;
                LDSM_X4_T(bh[np][0], bh[np][1], bh[np][2], bh[np][3], bd);
            }
            // term 1: hi — 16 independent MMAs
#pragma unroll
            for (int mt = 0; mt < 4; mt++)
#pragma unroll
                for (int nt = 0; nt < 4; nt++) {
                    int np = nt >> 1, wq = (nt & 1) * 2;
                    MMA16816(acc[mt][nt], ah[mt], bh[np][wq], bh[np][wq + 1]);
                }
            // term 2: lo — 16 independent MMAs
#pragma unroll
            for (int mt = 0; mt < 4; mt++)
#pragma unroll
                for (int nt = 0; nt < 4; nt++) {
                    int np = nt >> 1, wq = (nt & 1) * 2;
                    MMA16816(acc[mt][nt], al[mt], bh[np][wq], bh[np][wq + 1]);
                }
        }
    }
    __syncthreads();

    // ---- epilogue: stage C in SMEM (stride 132 f32), then coalesced out ----
    float* cs = (float*)smem;
#pragma unroll
    for (int mt = 0; mt < 4; mt++)
#pragma unroll
        for (int nt = 0; nt < 4; nt++) {
            int r = wm * 64 + mt * 16 + (lane >> 2);
            int cc = wn * 32 + nt * 8 + (lane & 3) * 2;
            cs[r * 132 + cc]           = acc[mt][nt][0];
            cs[r * 132 + cc + 1]       = acc[mt][nt][1];
            cs[(r + 8) * 132 + cc]     = acc[mt][nt][2];
            cs[(r + 8) * 132 + cc + 1] = acc[mt][nt][3];
        }
    __syncthreads();

#pragma unroll
    for (int i = 0; i < 16; i++) {
        int idx = t + 256 * i;           // 4096 float4s
        int r = idx >> 5, c4 = (idx & 31) * 4;
        float bias = bv[m0 + r];
        size_t off = ((size_t)bb * S + m0 + r) * D + n0 + c4;
        float4 xv = *(const float4*)(x + off);
        float4 ov;
        ov.x = gelu_f(cs[r * 132 + c4 + 0] + bias + xv.x);
        ov.y = gelu_f(cs[r * 132 + c4 + 1] + bias + xv.y);
        ov.z = gelu_f(cs[r * 132 + c4 + 2] + bias + xv.z);
        ov.w = gelu_f(cs[r * 132 + c4 + 3] + bias + xv.w);
        *(float4*)(out + off) = ov;
    }
}

// ---------------- launch ----------------
extern "C" void kernel_launch(void* const* d_in, const int* in_sizes, int n_in,
                              void* d_out, int out_size)
{
    const float* x    = (const float*)d_in[0];
    const float* ln_g = (const float*)d_in[1];
    const float* ln_b = (const float*)d_in[2];
    const float* w1   = (const float*)d_in[3];
    const float* b1   = (const float*)d_in[4];
    const float* wc   = (const float*)d_in[5];
    const float* bc   = (const float*)d_in[6];
    const float* w2   = (const float*)d_in[7];
    const float* b2   = (const float*)d_in[8];
    const float* Wi   = (const float*)d_in[9];
    const float* bi   = (const float*)d_in[10];
    const float* Wii  = (const float*)d_in[11];
    const float* bii  = (const float*)d_in[12];
    float* out = (float*)d_out;

    cudaFuncSetAttribute(k_gemm_mma, cudaFuncAttributeMaxDynamicSharedMemorySize, SMEM_BYTES);

    k_zero<<<1, 320>>>();
    k_split<<<S * S / 256, 256>>>(Wi, Wii);
    k_ln<<<B * S, 256>>>(x, ln_g, ln_b, w1, b1, wc);
    k_gate<<<1, 32>>>(bc, w2, b2);
    k_gemm_mma<<<dim3(D / BN, S / BM, B), 256, SMEM_BYTES>>>(bi, bii, x, out);
}

// round 10
// speedup vs baseline: 3.6943x; 1.3960x over previous
#include <cuda_runtime.h>
#include <cuda_fp16.h>
#include <math.h>
#include <stdint.h>

#define B 32
#define S 512
#define D 1536
#define D24 64
#define KF 10

// ---------------- device scratch (no allocation allowed) ----------------
__device__ __half g_xh[(size_t)B * S * D];   // xn in fp16
__device__ __half g_wh[2 * S * S];           // W in fp16 (Wi, Wii)
__device__ float g_acc[B * KF];
__device__ int   g_sel[B];

__device__ __forceinline__ float gelu_f(float v) {
    return 0.5f * v * (1.0f + erff(v * 0.7071067811865476f));
}
__device__ __forceinline__ uint32_t smem_u32(const void* p) {
    uint32_t a;
    asm("{ .reg .u64 t; cvta.to.shared.u64 t, %1; cvt.u32.u64 %0, t; }" : "=r"(a) : "l"(p));
    return a;
}

// ---------------- small kernels ----------------
__global__ void k_split(const float* __restrict__ Wi, const float* __restrict__ Wii) {
    int i = blockIdx.x * 256 + threadIdx.x;   // 0..262143
    g_wh[i]         = __float2half_rn(Wi[i]);
    g_wh[S * S + i] = __float2half_rn(Wii[i]);
    if (blockIdx.x == 0 && threadIdx.x < B * KF) g_acc[threadIdx.x] = 0.0f;
}

__global__ __launch_bounds__(256)
void k_ln(const float* __restrict__ x,
          const float* __restrict__ ln_g, const float* __restrict__ ln_b,
          const float* __restrict__ w1,   const float* __restrict__ b1,
          const float* __restrict__ wc)
{
    __shared__ float sh[D];
    __shared__ float rsum[8], rsq[8];
    __shared__ float s_mu, s_rs;

    int row = blockIdx.x;
    int b   = row >> 9;
    int s   = row & 511;
    const float* xr = x + (size_t)row * D;
    int t = threadIdx.x;

    float v[6];
    float sum = 0.f, sq = 0.f;
#pragma unroll
    for (int i = 0; i < 6; i++) {
        v[i] = xr[t + 256 * i];
        sum += v[i];
        sq  += v[i] * v[i];
    }
#pragma unroll
    for (int o = 16; o; o >>= 1) {
        sum += __shfl_xor_sync(0xffffffffu, sum, o);
        sq  += __shfl_xor_sync(0xffffffffu, sq,  o);
    }
    if ((t & 31) == 0) { rsum[t >> 5] = sum; rsq[t >> 5] = sq; }
    __syncthreads();
    if (t == 0) {
        float ts = 0.f, tq = 0.f;
#pragma unroll
        for (int i = 0; i < 8; i++) { ts += rsum[i]; tq += rsq[i]; }
        float mu  = ts * (1.0f / D);
        float var = tq * (1.0f / D) - mu * mu;
        s_mu = mu;
        s_rs = rsqrtf(var + 1e-5f);
    }
    __syncthreads();
    float mu = s_mu, rs = s_rs;

    __half* xh = g_xh + (size_t)row * D;
#pragma unroll
    for (int i = 0; i < 6; i++) {
        int idx = t + 256 * i;
        float xn = (v[i] - mu) * rs * ln_g[idx] + ln_b[idx];
        sh[idx] = xn;
        xh[idx] = __float2half_rn(xn);
    }
    __syncthreads();

    if (t < KF) {
        float d = b1[t];
#pragma unroll
        for (int j = 0; j < D24; j++) d += sh[j] * w1[j * KF + t];
        float h = gelu_f(d);
        atomicAdd(&g_acc[b * KF + t], wc[s] * h);
    }
}

__global__ void k_gate(const float* __restrict__ bc,
                       const float* __restrict__ w2,
                       const float* __restrict__ b2)
{
    int b = threadIdx.x;
    if (b < B) {
        float bcv = bc[0];
        float lg = b2[0];
#pragma unroll
        for (int k = 0; k < KF; k++)
            lg += gelu_f(g_acc[b * KF + k] + bcv) * w2[k];
        float g = 1.0f / (1.0f + expf(-lg));
        g_sel[b] = (rintf(g) != 0.0f) ? 1 : 0;
    }
}

// ---------------- HMMA (mma.sync fp16, single term) GEMM ----------------
// Per batch: C[s,d] = sum_t Wsel[s,t] * xn[t,d]; out = gelu(C + bias + residual)
// CTA 128x128, BK=32, 256 thr / 8 warps, warp tile 64x32, 4-stage cp.async.
#define BM 128
#define BN 128
#define BK 32
#define A_STRIDE 40                      // fp16 per A row (32 + 8 pad) = 80B
#define B_STRIDE 136                     // fp16 per B row (128 + 8 pad) = 272B
#define ABYTES (128 * A_STRIDE * 2)      // 10240
#define BBYTES (32 * B_STRIDE * 2)       // 8704
#define STAGE_BYTES (ABYTES + BBYTES)    // 18944
#define NSTAGE 4
#define SMEM_BYTES (NSTAGE * STAGE_BYTES) // 75776 (epilogue reuse: 128*132*4 = 67584)

#define LDSM_X4(r0, r1, r2, r3, a) \
    asm volatile("ldmatrix.sync.aligned.m8n8.x4.shared.b16 {%0,%1,%2,%3}, [%4];" \
        : "=r"(r0), "=r"(r1), "=r"(r2), "=r"(r3) : "r"(a))
#define LDSM_X4_T(r0, r1, r2, r3, a) \
    asm volatile("ldmatrix.sync.aligned.m8n8.x4.trans.shared.b16 {%0,%1,%2,%3}, [%4];" \
        : "=r"(r0), "=r"(r1), "=r"(r2), "=r"(r3) : "r"(a))
#define MMA16816(c, a, b0, b1) \
    asm volatile("mma.sync.aligned.m16n8k16.row.col.f32.f16.f16.f32 " \
        "{%0,%1,%2,%3}, {%4,%5,%6,%7}, {%8,%9}, {%0,%1,%2,%3};" \
        : "+f"((c)[0]), "+f"((c)[1]), "+f"((c)[2]), "+f"((c)[3]) \
        : "r"((a)[0]), "r"((a)[1]), "r"((a)[2]), "r"((a)[3]), "r"(b0), "r"(b1))
#define CP_ASYNC16(dst, src) \
    asm volatile("cp.async.cg.shared.global [%0], [%1], 16;" :: "r"(dst), "l"(src))

__global__ __launch_bounds__(256, 2)
void k_gemm_mma(const float* __restrict__ bi, const float* __restrict__ bii,
                const float* __restrict__ x,  float* __restrict__ out)
{
    extern __shared__ char smem[];
    uint32_t sb = smem_u32(smem);
    int t = threadIdx.x;
    int lane = t & 31;
    int wid = t >> 5;
    int wm = wid >> 2;        // 0..1 -> m offset wm*64
    int wn = wid & 3;         // 0..3 -> n offset wn*32
    int bb = blockIdx.z;
    int m0 = blockIdx.y * BM;
    int n0 = blockIdx.x * BN;

    int sel = g_sel[bb];
    const __half* wh = g_wh + (size_t)sel * S * S;
    const float* bv = sel ? bii : bi;
    const __half* xh = g_xh + (size_t)bb * S * D;

    // ---- async stage loader (4 x 16B per thread) ----
    auto load_stage = [&](int c, int st) {
        int k0 = c * BK;
        uint32_t base = sb + st * STAGE_BYTES;
#pragma unroll
        for (int i = 0; i < 2; i++) {           // A: 512 x 16B
            int idx = t + 256 * i;
            int row = idx >> 2, seg = idx & 3;
            const __half* src = wh + (size_t)(m0 + row) * S + k0 + seg * 8;
            uint32_t dst = base + (row * A_STRIDE + seg * 8) * 2;
            CP_ASYNC16(dst, src);
        }
#pragma unroll
        for (int i = 0; i < 2; i++) {           // B: 512 x 16B
            int idx = t + 256 * i;
            int row = idx >> 4, seg = idx & 15;
            const __half* src = xh + (size_t)(k0 + row) * D + n0 + seg * 8;
            uint32_t dst = base + ABYTES + (row * B_STRIDE + seg * 8) * 2;
            CP_ASYNC16(dst, src);
        }
        asm volatile("cp.async.commit_group;");
    };

    float acc[4][4][4];
#pragma unroll
    for (int i = 0; i < 4; i++)
#pragma unroll
        for (int j = 0; j < 4; j++)
#pragma unroll
            for (int k = 0; k < 4; k++) acc[i][j][k] = 0.f;

    load_stage(0, 0);
    load_stage(1, 1);
    load_stage(2, 2);

    for (int c = 0; c < 16; c++) {
        int st = c & 3;
        // drain so stage c is complete; keep up to 2 newer groups in flight
        if (c < 14)       asm volatile("cp.async.wait_group 2;");
        else if (c == 14) asm volatile("cp.async.wait_group 1;");
        else              asm volatile("cp.async.wait_group 0;");
        __syncthreads();
        if (c + 3 < 16) load_stage(c + 3, (c + 3) & 3);

        uint32_t base = sb + st * STAGE_BYTES;
#pragma unroll
        for (int ks = 0; ks < 2; ks++) {
            int kc = ks * 16 + (lane >> 4) * 8;           // ldmatrix k col
            uint32_t ah[4][4];
#pragma unroll
            for (int mt = 0; mt < 4; mt++) {
                int row = wm * 64 + mt * 16 + (lane & 15);
                uint32_t ad = base + (row * A_STRIDE + kc) * 2;
                LDSM_X4(ah[mt][0], ah[mt][1], ah[mt][2], ah[mt][3], ad);
            }
            uint32_t bh[2][4];
#pragma unroll
            for (int np = 0; np < 2; np++) {
                int krow = ks * 16 + (lane & 15);
                int coln = wn * 32 + np * 16 + (lane >> 4) * 8;
                uint32_t bd = base + ABYTES + (krow * B_STRIDE + coln) * 2;
                LDSM_X4_T(bh[np][0], bh[np][1], bh[np][2], bh[np][3], bd);
            }
#pragma unroll
            for (int mt = 0; mt < 4; mt++)
#pragma unroll
                for (int nt = 0; nt < 4; nt++) {
                    int np = nt >> 1, wq = (nt & 1) * 2;
                    MMA16816(acc[mt][nt], ah[mt], bh[np][wq], bh[np][wq + 1]);
                }
        }
    }
    __syncthreads();

    // ---- epilogue: stage C in SMEM (stride 132 f32), then coalesced out ----
    float* cs = (float*)smem;
#pragma unroll
    for (int mt = 0; mt < 4; mt++)
#pragma unroll
        for (int nt = 0; nt < 4; nt++) {
            int r = wm * 64 + mt * 16 + (lane >> 2);
            int cc = wn * 32 + nt * 8 + (lane & 3) * 2;
            cs[r * 132 + cc]           = acc[mt][nt][0];
            cs[r * 132 + cc + 1]       = acc[mt][nt][1];
            cs[(r + 8) * 132 + cc]     = acc[mt][nt][2];
            cs[(r + 8) * 132 + cc + 1] = acc[mt][nt][3];
        }
    __syncthreads();

#pragma unroll
    for (int i = 0; i < 16; i++) {
        int idx = t + 256 * i;           // 4096 float4s
        int r = idx >> 5, c4 = (idx & 31) * 4;
        float bias = bv[m0 + r];
        size_t off = ((size_t)bb * S + m0 + r) * D + n0 + c4;
        float4 xv = *(const float4*)(x + off);
        float4 ov;
        ov.x = gelu_f(cs[r * 132 + c4 + 0] + bias + xv.x);
        ov.y = gelu_f(cs[r * 132 + c4 + 1] + bias + xv.y);
        ov.z = gelu_f(cs[r * 132 + c4 + 2] + bias + xv.z);
        ov.w = gelu_f(cs[r * 132 + c4 + 3] + bias + xv.w);
        *(float4*)(out + off) = ov;
    }
}

// ---------------- launch ----------------
extern "C" void kernel_launch(void* const* d_in, const int* in_sizes, int n_in,
                              void* d_out, int out_size)
{
    const float* x    = (const float*)d_in[0];
    const float* ln_g = (const float*)d_in[1];
    const float* ln_b = (const float*)d_in[2];
    const float* w1   = (const float*)d_in[3];
    const float* b1   = (const float*)d_in[4];
    const float* wc   = (const float*)d_in[5];
    const float* bc   = (const float*)d_in[6];
    const float* w2   = (const float*)d_in[7];
    const float* b2   = (const float*)d_in[8];
    const float* Wi   = (const float*)d_in[9];
    const float* bi   = (const float*)d_in[10];
    const float* Wii  = (const float*)d_in[11];
    const float* bii  = (const float*)d_in[12];
    float* out = (float*)d_out;

    cudaFuncSetAttribute(k_gemm_mma, cudaFuncAttributeMaxDynamicSharedMemorySize, SMEM_BYTES);

    k_split<<<S * S / 256, 256>>>(Wi, Wii);
    k_ln<<<B * S, 256>>>(x, ln_g, ln_b, w1, b1, wc);
    k_gate<<<1, 32>>>(bc, w2, b2);
    k_gemm_mma<<<dim3(D / BN, S / BM, B), 256, SMEM_BYTES>>>(bi, bii, x, out);
}